// round 2
// baseline (speedup 1.0000x reference)
#include <cuda_runtime.h>
#include <math.h>

#define BB 8
#define TT 2048
#define DD 64
#define KTOP 5
#define BK (BB*KTOP)
#define UMAX 4094
#define TU 32
#define EPSBN 1e-5f

// ---------------- scratch (device globals; no allocs allowed) ----------------
__device__ float d_trend[BB*TT*DD];
__device__ float d_s[BB*TT*DD];
__device__ float d_pw[BB*DD*TT];
__device__ float d_Pm[BB*TT];
__device__ float d_r[BB*TT];
__device__ int   d_p[BK];
__device__ int   d_cyc[BK];
__device__ int   d_ucount[BK];
__device__ float d_wk[BK];
__device__ float d_G [BK*UMAX*DD];
__device__ float d_H1[BK*UMAX*DD];
__device__ float d_H2[BK*UMAX*DD];

// ---------------- 1. trend + seasonal ----------------
__global__ __launch_bounds__(256) void trend_kernel(const float* __restrict__ x) {
    int i = blockIdx.x * 256 + threadIdx.x;
    if (i >= BB*TT*DD) return;
    int c = i & 63;
    int t = (i >> 6) & (TT - 1);
    int b = i >> 17;
    int lo = t - 12; if (lo < 0) lo = 0;
    int hi = t + 12; if (hi > TT - 1) hi = TT - 1;
    const float* xb = x + ((size_t)b * TT) * DD + c;
    float sum = 0.f;
    for (int tt = lo; tt <= hi; tt++) sum += xb[(size_t)tt * DD];
    float tr = sum / (float)(hi - lo + 1);
    d_trend[i] = tr;
    d_s[i] = x[i] - tr;
}

// ---------------- 2. forward FFT + power per (b,c) ----------------
// Stockham radix-2, 2048-point complex FFT in shared memory.
__global__ __launch_bounds__(256) void fft_power_kernel() {
    __shared__ float2 bufA[2048];
    __shared__ float2 bufB[2048];
    int b = blockIdx.x >> 6;
    int c = blockIdx.x & 63;
    const float* sp = d_s + ((size_t)b * TT) * DD + c;
    for (int t = threadIdx.x; t < 2048; t += 256)
        bufA[t] = make_float2(sp[(size_t)t * DD], 0.f);
    __syncthreads();
    float2* src = bufA; float2* dst = bufB;
    for (int st = 0; st < 11; st++) {
        int m = 1 << st;
        int l = 1024 >> st;
        for (int i = threadIdx.x; i < 1024; i += 256) {
            int j = i >> st;
            float2 a = src[i];
            float2 bb = src[i + 1024];
            float2 s2 = make_float2(a.x + bb.x, a.y + bb.y);
            float2 d2 = make_float2(a.x - bb.x, a.y - bb.y);
            float ang = (-3.14159265358979323846f) * (float)j / (float)l;
            float sw, cw; sincosf(ang, &sw, &cw);
            int o = i + (i & ~(m - 1));
            dst[o]     = s2;
            dst[o + m] = make_float2(cw * d2.x - sw * d2.y, cw * d2.y + sw * d2.x);
        }
        __syncthreads();
        float2* tmp = src; src = dst; dst = tmp;
    }
    float* out = d_pw + (size_t)blockIdx.x * 2048;
    for (int t = threadIdx.x; t < 2048; t += 256) {
        float2 X = src[t];
        out[t] = X.x * X.x + X.y * X.y;
    }
}

// ---------------- 3. mean over channels ----------------
__global__ __launch_bounds__(256) void pow_reduce_kernel() {
    int i = blockIdx.x * 256 + threadIdx.x;
    if (i >= BB*TT) return;
    int b = i >> 11;
    int t = i & 2047;
    float sum = 0.f;
    const float* base = d_pw + ((size_t)b * DD) * 2048 + t;
    for (int c = 0; c < DD; c++) sum += base[(size_t)c * 2048];
    d_Pm[i] = sum * (1.f / DD);
}

// ---------------- 4. inverse FFT -> autocorrelation r (exactly symmetrized) --
__global__ __launch_bounds__(256) void ifft_kernel() {
    __shared__ float2 bufA[2048];
    __shared__ float2 bufB[2048];
    int b = blockIdx.x;
    const float* P = d_Pm + (size_t)b * 2048;
    for (int t = threadIdx.x; t < 2048; t += 256)
        bufA[t] = make_float2(P[t], 0.f);
    __syncthreads();
    float2* src = bufA; float2* dst = bufB;
    for (int st = 0; st < 11; st++) {
        int m = 1 << st;
        int l = 1024 >> st;
        for (int i = threadIdx.x; i < 1024; i += 256) {
            int j = i >> st;
            float2 a = src[i];
            float2 bb = src[i + 1024];
            float2 s2 = make_float2(a.x + bb.x, a.y + bb.y);
            float2 d2 = make_float2(a.x - bb.x, a.y - bb.y);
            float ang = (-3.14159265358979323846f) * (float)j / (float)l;
            float sw, cw; sincosf(ang, &sw, &cw);
            int o = i + (i & ~(m - 1));
            dst[o]     = s2;
            dst[o + m] = make_float2(cw * d2.x - sw * d2.y, cw * d2.y + sw * d2.x);
        }
        __syncthreads();
        float2* tmp = src; src = dst; dst = tmp;
    }
    // r[t] symmetric by construction: take t<=1024 and mirror (jax ties then
    // break to the lower index, which the top-k kernel reproduces).
    for (int t = threadIdx.x; t < 2048; t += 256) {
        int ts = (t <= 1024) ? t : (2048 - t);
        d_r[(size_t)b * 2048 + t] = src[ts].x * (1.f / 2048.f);
    }
}

// ---------------- 5. top-k + softmax + period metadata ----------------
__global__ __launch_bounds__(256) void topk_kernel() {
    int b = blockIdx.x;
    __shared__ float rv[2048];
    __shared__ float redv[256];
    __shared__ int   redi[256];
    __shared__ float vals[KTOP];
    int tid = threadIdx.x;
    for (int t = tid; t < 2048; t += 256) rv[t] = d_r[(size_t)b * 2048 + t];
    __syncthreads();
    if (tid == 0) rv[0] = -INFINITY;
    __syncthreads();
    for (int sel = 0; sel < KTOP; sel++) {
        float bv = -INFINITY; int bi = 0;
        for (int t = tid; t < 2048; t += 256) {
            float v = rv[t];
            if (v > bv) { bv = v; bi = t; }
        }
        redv[tid] = bv; redi[tid] = bi;
        __syncthreads();
        for (int off = 128; off > 0; off >>= 1) {
            if (tid < off) {
                float v2 = redv[tid + off]; int i2 = redi[tid + off];
                if (v2 > redv[tid] || (v2 == redv[tid] && i2 < redi[tid])) {
                    redv[tid] = v2; redi[tid] = i2;
                }
            }
            __syncthreads();
        }
        if (tid == 0) {
            vals[sel] = redv[0];
            int p = redi[0];
            int bk = b * KTOP + sel;
            d_p[bk] = p;
            int cyc = (TT + p - 1) / p;
            d_cyc[bk] = cyc;
            d_ucount[bk] = cyc * p;
            rv[p] = -INFINITY;
        }
        __syncthreads();
    }
    if (tid == 0) {
        float m = vals[0];
        for (int s = 1; s < KTOP; s++) m = fmaxf(m, vals[s]);
        float e[KTOP], sum = 0.f;
        for (int s = 0; s < KTOP; s++) { e[s] = expf(vals[s] - m); sum += e[s]; }
        for (int s = 0; s < KTOP; s++) d_wk[b * KTOP + s] = e[s] / sum;
    }
}

// ---------------- 6. gather g = roll+reflect+fold ----------------
__global__ __launch_bounds__(256) void gather_kernel() {
    int bk = blockIdx.y;
    int ucount = d_ucount[bk];
    int p = d_p[bk];
    int b = bk / KTOP;
    int i = blockIdx.x * 256 + threadIdx.x;
    if (i >= UMAX * DD) return;
    int u = i >> 6;
    int c = i & 63;
    if (u >= ucount) return;
    int v = (u < TT) ? u : (2 * TT - 2 - u);
    int t = v + p;
    if (t >= TT) t -= TT;
    d_G[(size_t)bk * (UMAX * DD) + i] = d_s[((size_t)b * TT + t) * DD + c];
}

// ---------------- 7. 3x3 grid conv + BN (+GELU) ----------------
__global__ __launch_bounds__(256) void conv_kernel(
    const float* __restrict__ in, float* __restrict__ out,
    const float* __restrict__ W,
    const float* __restrict__ gamma, const float* __restrict__ beta,
    const float* __restrict__ mean,  const float* __restrict__ var,
    int dogelu)
{
    int bk = blockIdx.y;
    int ucount = d_ucount[bk];
    int u0 = blockIdx.x * TU;
    if (u0 >= ucount) return;
    int p = d_p[bk];
    int cyc = d_cyc[bk];

    __shared__ float Gsh[3][TU + 2][DD];
    __shared__ float Wsh[8][9][DD];

    int tid = threadIdx.x;
    const float* base = in + (size_t)bk * (UMAX * DD);

    // stage the 3 row segments (dr = -1, 0, +1)
    for (int i = tid; i < 3 * (TU + 2) * DD; i += 256) {
        int seg = i / ((TU + 2) * DD);
        int rem = i - seg * ((TU + 2) * DD);
        int row = rem >> 6;
        int c = rem & 63;
        int gu = u0 + (seg - 1) * p - 1 + row;
        Gsh[seg][row][c] = ((unsigned)gu < (unsigned)ucount)
                               ? base[(size_t)gu * DD + c] : 0.f;
    }

    int cout = tid & 63;
    int us = tid >> 6;            // 0..3

    unsigned vmask[8];
    int du[8];
#pragma unroll
    for (int it = 0; it < 8; it++) {
        int u = u0 + it * 4 + us;
        du[it] = u - u0;
        unsigned msk = 0;
        if (u < ucount) {
            int rr = u / p, cc = u - (u / p) * p;
#pragma unroll
            for (int tap = 0; tap < 9; tap++) {
                int dr = tap / 3 - 1, dc = tap % 3 - 1;
                if ((unsigned)(rr + dr) < (unsigned)cyc &&
                    (unsigned)(cc + dc) < (unsigned)p)
                    msk |= 1u << tap;
            }
        }
        vmask[it] = msk;
    }

    float acc[8];
#pragma unroll
    for (int it = 0; it < 8; it++) acc[it] = 0.f;

    for (int ch = 0; ch < 8; ch++) {
        __syncthreads();
        for (int i = tid; i < 8 * 9 * DD; i += 256) {
            int co = i & 63;
            int rest = i >> 6;        // cin_local*9 + tap
            int cl = rest / 9, tap = rest - cl * 9;
            Wsh[cl][tap][co] = W[((size_t)(co * DD + ch * 8 + cl)) * 9 + tap];
        }
        __syncthreads();
        int ch8 = ch * 8;
#pragma unroll
        for (int tap = 0; tap < 9; tap++) {
            float wr[8];
#pragma unroll
            for (int ci = 0; ci < 8; ci++) wr[ci] = Wsh[ci][tap][cout];
            int seg = tap / 3;
            int dc1 = tap - seg * 3;
#pragma unroll
            for (int it = 0; it < 8; it++) {
                if ((vmask[it] >> tap) & 1u) {
                    const float* gp = &Gsh[seg][du[it] + dc1][ch8];
                    float4 g0 = *(const float4*)gp;
                    float4 g1 = *(const float4*)(gp + 4);
                    acc[it] += g0.x * wr[0] + g0.y * wr[1] + g0.z * wr[2] + g0.w * wr[3]
                             + g1.x * wr[4] + g1.y * wr[5] + g1.z * wr[6] + g1.w * wr[7];
                }
            }
        }
    }

    float sc = gamma[cout] * rsqrtf(var[cout] + EPSBN);
    float sh = beta[cout] - mean[cout] * sc;
#pragma unroll
    for (int it = 0; it < 8; it++) {
        int u = u0 + it * 4 + us;
        if (u >= ucount) continue;
        float v = acc[it] * sc + sh;
        if (dogelu) v = 0.5f * v * (1.f + erff(v * 0.70710678118654752f));
        out[(size_t)bk * (UMAX * DD) + (size_t)u * DD + cout] = v;
    }
}

// ---------------- 8. weighted aggregation + residual ----------------
__global__ __launch_bounds__(256) void finalize_kernel(const float* __restrict__ x,
                                                       float* __restrict__ out) {
    int i = blockIdx.x * 256 + threadIdx.x;
    if (i >= BB*TT*DD) return;
    int b = i >> 17;
    int tc = i & (TT * DD - 1);
    float acc = x[i] + d_trend[i];
#pragma unroll
    for (int k = 0; k < KTOP; k++) {
        int bk = b * KTOP + k;
        size_t o = (size_t)bk * (UMAX * DD) + tc;
        acc += d_wk[bk] * (d_G[o] + d_H2[o]);
    }
    out[i] = acc;
}

// ---------------- launch ----------------
extern "C" void kernel_launch(void* const* d_in, const int* in_sizes, int n_in,
                              void* d_out, int out_size) {
    const float* x        = (const float*)d_in[0];
    const float* w1       = (const float*)d_in[1];
    const float* w2       = (const float*)d_in[2];
    const float* bn1_g    = (const float*)d_in[3];
    const float* bn1_b    = (const float*)d_in[4];
    const float* bn1_m    = (const float*)d_in[5];
    const float* bn1_v    = (const float*)d_in[6];
    const float* bn2_g    = (const float*)d_in[7];
    const float* bn2_b    = (const float*)d_in[8];
    const float* bn2_m    = (const float*)d_in[9];
    const float* bn2_v    = (const float*)d_in[10];
    float* out = (float*)d_out;

    float* G;  cudaGetSymbolAddress((void**)&G,  d_G);
    float* H1; cudaGetSymbolAddress((void**)&H1, d_H1);
    float* H2; cudaGetSymbolAddress((void**)&H2, d_H2);

    trend_kernel<<<(BB*TT*DD + 255) / 256, 256>>>(x);
    fft_power_kernel<<<BB * DD, 256>>>();
    pow_reduce_kernel<<<(BB*TT + 255) / 256, 256>>>();
    ifft_kernel<<<BB, 256>>>();
    topk_kernel<<<BB, 256>>>();
    gather_kernel<<<dim3((UMAX * DD + 255) / 256, BK), 256>>>();
    conv_kernel<<<dim3((UMAX + TU - 1) / TU, BK), 256>>>(G, H1, w1, bn1_g, bn1_b, bn1_m, bn1_v, 1);
    conv_kernel<<<dim3((UMAX + TU - 1) / TU, BK), 256>>>(H1, H2, w2, bn2_g, bn2_b, bn2_m, bn2_v, 0);
    finalize_kernel<<<(BB*TT*DD + 255) / 256, 256>>>(x, out);
}

// round 8
// speedup vs baseline: 2.8870x; 2.8870x over previous
#include <cuda_runtime.h>
#include <math.h>
#include <stdint.h>

#define BB 8
#define TT 2048
#define DD 64
#define KTOP 5
#define BK (BB*KTOP)
#define UMAX 4094
#define EPSBN 1e-5f

// ---------------- scratch (device globals; no allocs allowed) ----------------
__device__ float d_trend[BB*TT*DD];
__device__ float d_s[BB*TT*DD];
__device__ float d_pw[BB*DD*TT];
__device__ float d_Pm[BB*TT];
__device__ float d_r[BB*TT];
__device__ int   d_p[BK];
__device__ int   d_cyc[BK];
__device__ int   d_ucount[BK];
__device__ float d_wk[BK];
__device__ float d_G [BK*UMAX*DD];
__device__ float d_H1[BK*UMAX*DD];
__device__ float d_H2[BK*UMAX*DD];

// ---------------- 1. trend + seasonal ----------------
__global__ __launch_bounds__(256) void trend_kernel(const float* __restrict__ x) {
    int i = blockIdx.x * 256 + threadIdx.x;
    if (i >= BB*TT*DD) return;
    int c = i & 63;
    int t = (i >> 6) & (TT - 1);
    int b = i >> 17;
    int lo = t - 12; if (lo < 0) lo = 0;
    int hi = t + 12; if (hi > TT - 1) hi = TT - 1;
    const float* xb = x + ((size_t)b * TT) * DD + c;
    float sum = 0.f;
    for (int tt = lo; tt <= hi; tt++) sum += xb[(size_t)tt * DD];
    float tr = sum / (float)(hi - lo + 1);
    d_trend[i] = tr;
    d_s[i] = x[i] - tr;
}

// ---------------- 2. forward FFT + power per (b,c) ----------------
__global__ __launch_bounds__(256) void fft_power_kernel() {
    __shared__ float2 bufA[2048];
    __shared__ float2 bufB[2048];
    int b = blockIdx.x >> 6;
    int c = blockIdx.x & 63;
    const float* sp = d_s + ((size_t)b * TT) * DD + c;
    for (int t = threadIdx.x; t < 2048; t += 256)
        bufA[t] = make_float2(sp[(size_t)t * DD], 0.f);
    __syncthreads();
    float2* src = bufA; float2* dst = bufB;
    for (int st = 0; st < 11; st++) {
        int m = 1 << st;
        int l = 1024 >> st;
        for (int i = threadIdx.x; i < 1024; i += 256) {
            int j = i >> st;
            float2 a = src[i];
            float2 bb = src[i + 1024];
            float2 s2 = make_float2(a.x + bb.x, a.y + bb.y);
            float2 d2 = make_float2(a.x - bb.x, a.y - bb.y);
            float ang = (-3.14159265358979323846f) * (float)j / (float)l;
            float sw, cw; sincosf(ang, &sw, &cw);
            int o = i + (i & ~(m - 1));
            dst[o]     = s2;
            dst[o + m] = make_float2(cw * d2.x - sw * d2.y, cw * d2.y + sw * d2.x);
        }
        __syncthreads();
        float2* tmp = src; src = dst; dst = tmp;
    }
    float* out = d_pw + (size_t)blockIdx.x * 2048;
    for (int t = threadIdx.x; t < 2048; t += 256) {
        float2 X = src[t];
        out[t] = X.x * X.x + X.y * X.y;
    }
}

// ---------------- 3. mean over channels ----------------
__global__ __launch_bounds__(256) void pow_reduce_kernel() {
    int i = blockIdx.x * 256 + threadIdx.x;
    if (i >= BB*TT) return;
    int b = i >> 11;
    int t = i & 2047;
    float sum = 0.f;
    const float* base = d_pw + ((size_t)b * DD) * 2048 + t;
    for (int c = 0; c < DD; c++) sum += base[(size_t)c * 2048];
    d_Pm[i] = sum * (1.f / DD);
}

// ---------------- 4. inverse FFT -> autocorrelation ----------------
__global__ __launch_bounds__(256) void ifft_kernel() {
    __shared__ float2 bufA[2048];
    __shared__ float2 bufB[2048];
    int b = blockIdx.x;
    const float* P = d_Pm + (size_t)b * 2048;
    for (int t = threadIdx.x; t < 2048; t += 256)
        bufA[t] = make_float2(P[t], 0.f);
    __syncthreads();
    float2* src = bufA; float2* dst = bufB;
    for (int st = 0; st < 11; st++) {
        int m = 1 << st;
        int l = 1024 >> st;
        for (int i = threadIdx.x; i < 1024; i += 256) {
            int j = i >> st;
            float2 a = src[i];
            float2 bb = src[i + 1024];
            float2 s2 = make_float2(a.x + bb.x, a.y + bb.y);
            float2 d2 = make_float2(a.x - bb.x, a.y - bb.y);
            float ang = (-3.14159265358979323846f) * (float)j / (float)l;
            float sw, cw; sincosf(ang, &sw, &cw);
            int o = i + (i & ~(m - 1));
            dst[o]     = s2;
            dst[o + m] = make_float2(cw * d2.x - sw * d2.y, cw * d2.y + sw * d2.x);
        }
        __syncthreads();
        float2* tmp = src; src = dst; dst = tmp;
    }
    for (int t = threadIdx.x; t < 2048; t += 256) {
        int ts = (t <= 1024) ? t : (2048 - t);
        d_r[(size_t)b * 2048 + t] = src[ts].x * (1.f / 2048.f);
    }
}

// ---------------- 5. top-k + softmax ----------------
__global__ __launch_bounds__(256) void topk_kernel() {
    int b = blockIdx.x;
    __shared__ float rv[2048];
    __shared__ float redv[256];
    __shared__ int   redi[256];
    __shared__ float vals[KTOP];
    int tid = threadIdx.x;
    for (int t = tid; t < 2048; t += 256) rv[t] = d_r[(size_t)b * 2048 + t];
    __syncthreads();
    if (tid == 0) rv[0] = -INFINITY;
    __syncthreads();
    for (int sel = 0; sel < KTOP; sel++) {
        float bv = -INFINITY; int bi = 0;
        for (int t = tid; t < 2048; t += 256) {
            float v = rv[t];
            if (v > bv) { bv = v; bi = t; }
        }
        redv[tid] = bv; redi[tid] = bi;
        __syncthreads();
        for (int off = 128; off > 0; off >>= 1) {
            if (tid < off) {
                float v2 = redv[tid + off]; int i2 = redi[tid + off];
                if (v2 > redv[tid] || (v2 == redv[tid] && i2 < redi[tid])) {
                    redv[tid] = v2; redi[tid] = i2;
                }
            }
            __syncthreads();
        }
        if (tid == 0) {
            vals[sel] = redv[0];
            int p = redi[0];
            int bk = b * KTOP + sel;
            d_p[bk] = p;
            int cyc = (TT + p - 1) / p;
            d_cyc[bk] = cyc;
            d_ucount[bk] = cyc * p;
            rv[p] = -INFINITY;
        }
        __syncthreads();
    }
    if (tid == 0) {
        float m = vals[0];
        for (int s = 1; s < KTOP; s++) m = fmaxf(m, vals[s]);
        float e[KTOP], sum = 0.f;
        for (int s = 0; s < KTOP; s++) { e[s] = expf(vals[s] - m); sum += e[s]; }
        for (int s = 0; s < KTOP; s++) d_wk[b * KTOP + s] = e[s] / sum;
    }
}

// ---------------- 6. gather ----------------
__global__ __launch_bounds__(256) void gather_kernel() {
    int bk = blockIdx.y;
    int ucount = d_ucount[bk];
    int p = d_p[bk];
    int b = bk / KTOP;
    int i = blockIdx.x * 256 + threadIdx.x;
    if (i >= UMAX * DD) return;
    int u = i >> 6;
    int c = i & 63;
    if (u >= ucount) return;
    int v = (u < TT) ? u : (2 * TT - 2 - u);
    int t = v + p;
    if (t >= TT) t -= TT;
    d_G[(size_t)bk * (UMAX * DD) + i] = d_s[((size_t)b * TT + t) * DD + c];
}

// ---------------- 7. mma.sync tf32 implicit-GEMM conv + BN (+GELU) -----------
// smem layout (dynamic):
//   [0      : 512)    BN scale/shift (64+64 floats)
//   [512    : 166400) W tiles: 9 taps x [cin 64][cout 64], stride 72 (tf32 bits)
//   [166400 : 201216) A tile: [u 128][k 64], stride 68 (tf32 bits)
#define CW_BN 0
#define CW_W  512
#define CW_A  166400
#define CW_TOTAL 201216
#define WSTR 72
#define ASTR 68

__device__ __forceinline__ uint32_t f2tf32(float f) {
    uint32_t o;
    asm("cvt.rna.tf32.f32 %0, %1;" : "=r"(o) : "f"(f));
    return o;
}

__global__ __launch_bounds__(256, 1) void conv_mma_kernel(
    const float* __restrict__ in, float* __restrict__ out,
    const float* __restrict__ W,
    const float* __restrict__ gamma, const float* __restrict__ beta,
    const float* __restrict__ mean,  const float* __restrict__ var,
    int dogelu)
{
    extern __shared__ char smem[];
    float*    bn = (float*)(smem + CW_BN);
    uint32_t* Ws = (uint32_t*)(smem + CW_W);
    uint32_t* As = (uint32_t*)(smem + CW_A);

    int tid = threadIdx.x, wid = tid >> 5, lid = tid & 31;
    int gid = lid >> 2, tg = lid & 3;   // fragment group / thread-in-group
    int wm = wid >> 1, wn = wid & 1;    // 4 x 2 warp grid
    int bk = blockIdx.y;
    int ucount = d_ucount[bk];
    int p = d_p[bk];
    int cyc = d_cyc[bk];

    if (tid < 64) {
        float sc = gamma[tid] * rsqrtf(var[tid] + EPSBN);
        bn[tid]      = sc;
        bn[64 + tid] = beta[tid] - mean[tid] * sc;
    }
    // stage all 9 weight tiles, tf32-converted: Ws[tap][cin][cout]
    for (int pp = tid; pp < 64 * 64; pp += 256) {
        int cout = pp & 63, cin = pp >> 6;
        const float* wp = W + ((size_t)(cout * 64 + cin)) * 9;
#pragma unroll
        for (int tap = 0; tap < 9; tap++)
            Ws[tap * (64 * WSTR) + cin * WSTR + cout] = f2tf32(wp[tap]);
    }

    int urow = tid >> 1;              // builder row 0..127
    int k0 = (tid & 1) * 32;          // builder column half

    for (int ti = blockIdx.x; ti * 128 < ucount; ti += 8) {
        int u0 = ti * 128;
        int u = u0 + urow;
        bool inb = u < ucount;
        int r = inb ? (u / p) : 0;
        int c = u - r * p;

        float dacc[2][4][4];
#pragma unroll
        for (int mf = 0; mf < 2; mf++)
#pragma unroll
            for (int nf = 0; nf < 4; nf++)
#pragma unroll
                for (int j = 0; j < 4; j++) dacc[mf][nf][j] = 0.f;

#pragma unroll
        for (int tap = 0; tap < 9; tap++) {
            int dr = tap / 3 - 1;
            int dc = tap - (tap / 3) * 3 - 1;
            __syncthreads();
            // build A tile (masked, shifted, tf32)
            {
                bool valid = inb &&
                             (unsigned)(r + dr) < (unsigned)cyc &&
                             (unsigned)(c + dc) < (unsigned)p;
                int gu = valid ? (u + dr * p + dc) : 0;
                const float4* src =
                    (const float4*)(in + ((size_t)bk * UMAX + gu) * 64 + k0);
                uint32_t* arow = As + urow * ASTR + k0;
#pragma unroll
                for (int f = 0; f < 8; f++) {
                    float4 v = valid ? src[f] : make_float4(0.f, 0.f, 0.f, 0.f);
                    uint4 o;
                    o.x = f2tf32(v.x); o.y = f2tf32(v.y);
                    o.z = f2tf32(v.z); o.w = f2tf32(v.w);
                    *(uint4*)(arow + f * 4) = o;
                }
            }
            __syncthreads();
            // GEMM: 8 k-steps of m16n8k8
            const uint32_t* wt = Ws + tap * (64 * WSTR);
            int arow0 = wm * 32 + gid;
#pragma unroll
            for (int kk = 0; kk < 8; kk++) {
                int kbase = kk * 8;
                uint32_t a[2][4];
#pragma unroll
                for (int mf = 0; mf < 2; mf++) {
                    const uint32_t* ap = As + (arow0 + mf * 16) * ASTR + kbase + tg;
                    a[mf][0] = ap[0];
                    a[mf][1] = ap[8 * ASTR];
                    a[mf][2] = ap[4];
                    a[mf][3] = ap[8 * ASTR + 4];
                }
#pragma unroll
                for (int nf = 0; nf < 4; nf++) {
                    int ncol = wn * 32 + nf * 8 + gid;
                    uint32_t b0 = wt[(kbase + tg) * WSTR + ncol];
                    uint32_t b1 = wt[(kbase + tg + 4) * WSTR + ncol];
#pragma unroll
                    for (int mf = 0; mf < 2; mf++) {
                        asm volatile(
                            "mma.sync.aligned.m16n8k8.row.col.f32.tf32.tf32.f32 "
                            "{%0,%1,%2,%3}, {%4,%5,%6,%7}, {%8,%9}, {%0,%1,%2,%3};"
                            : "+f"(dacc[mf][nf][0]), "+f"(dacc[mf][nf][1]),
                              "+f"(dacc[mf][nf][2]), "+f"(dacc[mf][nf][3])
                            : "r"(a[mf][0]), "r"(a[mf][1]), "r"(a[mf][2]), "r"(a[mf][3]),
                              "r"(b0), "r"(b1));
                    }
                }
            }
        }

        // epilogue: BN (+GELU) + store
#pragma unroll
        for (int mf = 0; mf < 2; mf++) {
            int row0 = u0 + wm * 32 + mf * 16 + gid;
#pragma unroll
            for (int nf = 0; nf < 4; nf++) {
                int col = wn * 32 + nf * 8 + 2 * tg;
                float sc0 = bn[col], sh0 = bn[64 + col];
                float sc1 = bn[col + 1], sh1 = bn[64 + col + 1];
#pragma unroll
                for (int h = 0; h < 2; h++) {
                    int row = row0 + h * 8;
                    if (row >= ucount) continue;
                    float v0 = dacc[mf][nf][2 * h]     * sc0 + sh0;
                    float v1 = dacc[mf][nf][2 * h + 1] * sc1 + sh1;
                    if (dogelu) {
                        v0 = 0.5f * v0 * (1.f + erff(v0 * 0.7071067811865475f));
                        v1 = 0.5f * v1 * (1.f + erff(v1 * 0.7071067811865475f));
                    }
                    float2 o2; o2.x = v0; o2.y = v1;
                    *(float2*)(out + ((size_t)bk * UMAX + row) * 64 + col) = o2;
                }
            }
        }
        __syncthreads();
    }
}

// ---------------- 8. weighted aggregation + residual ----------------
__global__ __launch_bounds__(256) void finalize_kernel(const float* __restrict__ x,
                                                       float* __restrict__ out) {
    int i = blockIdx.x * 256 + threadIdx.x;
    if (i >= BB*TT*DD) return;
    int b = i >> 17;
    int tc = i & (TT * DD - 1);
    float acc = x[i] + d_trend[i];
#pragma unroll
    for (int k = 0; k < KTOP; k++) {
        int bk = b * KTOP + k;
        size_t o = (size_t)bk * (UMAX * DD) + tc;
        acc += d_wk[bk] * (d_G[o] + d_H2[o]);
    }
    out[i] = acc;
}

// ---------------- launch ----------------
extern "C" void kernel_launch(void* const* d_in, const int* in_sizes, int n_in,
                              void* d_out, int out_size) {
    const float* x        = (const float*)d_in[0];
    const float* w1       = (const float*)d_in[1];
    const float* w2       = (const float*)d_in[2];
    const float* bn1_g    = (const float*)d_in[3];
    const float* bn1_b    = (const float*)d_in[4];
    const float* bn1_m    = (const float*)d_in[5];
    const float* bn1_v    = (const float*)d_in[6];
    const float* bn2_g    = (const float*)d_in[7];
    const float* bn2_b    = (const float*)d_in[8];
    const float* bn2_m    = (const float*)d_in[9];
    const float* bn2_v    = (const float*)d_in[10];
    float* out = (float*)d_out;

    float* G;  cudaGetSymbolAddress((void**)&G,  d_G);
    float* H1; cudaGetSymbolAddress((void**)&H1, d_H1);
    float* H2; cudaGetSymbolAddress((void**)&H2, d_H2);

    cudaFuncSetAttribute(conv_mma_kernel,
                         cudaFuncAttributeMaxDynamicSharedMemorySize, CW_TOTAL);

    trend_kernel<<<(BB*TT*DD + 255) / 256, 256>>>(x);
    fft_power_kernel<<<BB * DD, 256>>>();
    pow_reduce_kernel<<<(BB*TT + 255) / 256, 256>>>();
    ifft_kernel<<<BB, 256>>>();
    topk_kernel<<<BB, 256>>>();
    gather_kernel<<<dim3((UMAX * DD + 255) / 256, BK), 256>>>();
    conv_mma_kernel<<<dim3(8, BK), 256, CW_TOTAL>>>(G, H1, w1, bn1_g, bn1_b, bn1_m, bn1_v, 1);
    conv_mma_kernel<<<dim3(8, BK), 256, CW_TOTAL>>>(H1, H2, w2, bn2_g, bn2_b, bn2_m, bn2_v, 0);
    finalize_kernel<<<(BB*TT*DD + 255) / 256, 256>>>(x, out);
}

// round 9
// speedup vs baseline: 5.1201x; 1.7735x over previous
#include <cuda_runtime.h>
#include <math.h>
#include <stdint.h>

#define BB 8
#define TT 2048
#define DD 64
#define KTOP 5
#define BK (BB*KTOP)
#define UMAX 4094
#define EPSBN 1e-5f
#define ASTR 68

// ---------------- scratch (device globals; no allocs allowed) ----------------
__device__ float d_trend[BB*TT*DD];
__device__ float d_s[BB*TT*DD];
__device__ float d_pw[BB*DD*TT];
__device__ float d_Pm[BB*TT];
__device__ float d_r[BB*TT];
__device__ int   d_p[BK];
__device__ int   d_cyc[BK];
__device__ int   d_ucount[BK];
__device__ float d_wk[BK];
__device__ float d_G [BK*UMAX*DD];
__device__ float d_H1[BK*UMAX*DD];
__device__ float d_H2[BK*UMAX*DD];
__device__ float2 d_tw[2048];                 // twiddle table: tw[l+j] = exp(-i*pi*j/l)
__device__ uint2  d_WF[2*9*8*8*32];           // per-lane tf32 B-frags: [conv][tap][kk][nf2][lane]

__device__ __forceinline__ uint32_t f2tf32(float f) {
    uint32_t o;
    asm("cvt.rna.tf32.f32 %0, %1;" : "=r"(o) : "f"(f));
    return o;
}

// ---------------- 0a. twiddle table ----------------
__global__ __launch_bounds__(256) void twiddle_kernel() {
    int i = blockIdx.x * 256 + threadIdx.x;
    if (i >= 2048) return;
    if (i == 0) { d_tw[0] = make_float2(1.f, 0.f); return; }
    int l = 1 << (31 - __clz(i));
    int j = i - l;
    float ang = (-3.14159265358979323846f) * (float)j / (float)l;
    float sw, cw; sincosf(ang, &sw, &cw);
    d_tw[i] = make_float2(cw, sw);
}

// ---------------- 0b. weight fragment table ----------------
// d_WF[((cw*9+tap)*8+kk)*8+nf2][lane] : b0/b1 for mma (tf32)
__global__ __launch_bounds__(256) void wfrag_kernel(const float* __restrict__ w1,
                                                    const float* __restrict__ w2) {
    int i = blockIdx.x * 256 + threadIdx.x;
    if (i >= 2*9*8*8*32) return;
    int lane = i & 31;
    int nf2  = (i >> 5) & 7;
    int kk   = (i >> 8) & 7;
    int tap  = (i >> 11) % 9;
    int cw   = i / (9*8*8*32);
    const float* W = cw ? w2 : w1;
    int ncol = nf2 * 8 + (lane >> 2);
    int cin0 = kk * 8 + (lane & 3);
    uint2 v;
    v.x = f2tf32(W[((size_t)(ncol * 64 + cin0)) * 9 + tap]);
    v.y = f2tf32(W[((size_t)(ncol * 64 + cin0 + 4)) * 9 + tap]);
    d_WF[i] = v;
}

// ---------------- 1. trend + seasonal ----------------
__global__ __launch_bounds__(256) void trend_kernel(const float* __restrict__ x) {
    int i = blockIdx.x * 256 + threadIdx.x;
    if (i >= BB*TT*DD) return;
    int c = i & 63;
    int t = (i >> 6) & (TT - 1);
    int b = i >> 17;
    int lo = t - 12; if (lo < 0) lo = 0;
    int hi = t + 12; if (hi > TT - 1) hi = TT - 1;
    const float* xb = x + ((size_t)b * TT) * DD + c;
    float sum = 0.f;
    for (int tt = lo; tt <= hi; tt++) sum += xb[(size_t)tt * DD];
    float tr = sum / (float)(hi - lo + 1);
    d_trend[i] = tr;
    d_s[i] = x[i] - tr;
}

// ---------------- 2. forward FFT (2 channels packed) + power ----------------
// block = (b, pair); pair pr covers channels 2pr, 2pr+1 packed as complex.
// Output pw[t] = (|X[t]|^2 + |X[N-t]|^2)/2 = |FFT(ch0)[t]|^2 + |FFT(ch1)[t]|^2.
__global__ __launch_bounds__(256) void fft_power_kernel() {
    __shared__ float2 bufA[2048];
    __shared__ float2 bufB[2048];
    int b = blockIdx.x >> 5;
    int pr = blockIdx.x & 31;
    const float2* sp = (const float2*)d_s + ((size_t)b * TT) * 32 + pr;
    for (int t = threadIdx.x; t < 2048; t += 256)
        bufA[t] = sp[(size_t)t * 32];
    __syncthreads();
    float2* src = bufA; float2* dst = bufB;
    for (int st = 0; st < 11; st++) {
        int m = 1 << st;
        int l = 1024 >> st;
        for (int i = threadIdx.x; i < 1024; i += 256) {
            int j = i >> st;
            float2 a = src[i];
            float2 bb = src[i + 1024];
            float2 s2 = make_float2(a.x + bb.x, a.y + bb.y);
            float2 d2 = make_float2(a.x - bb.x, a.y - bb.y);
            float2 w = d_tw[l + j];
            int o = i + (i & ~(m - 1));
            dst[o]     = s2;
            dst[o + m] = make_float2(w.x * d2.x - w.y * d2.y, w.x * d2.y + w.y * d2.x);
        }
        __syncthreads();
        float2* tmp = src; src = dst; dst = tmp;
    }
    float* out = d_pw + (size_t)blockIdx.x * 2048;
    for (int t = threadIdx.x; t < 2048; t += 256) {
        float2 X0 = src[t];
        float2 X1 = src[(2048 - t) & 2047];
        out[t] = 0.5f * (X0.x * X0.x + X0.y * X0.y + X1.x * X1.x + X1.y * X1.y);
    }
}

// ---------------- 3. mean over channel pairs ----------------
__global__ __launch_bounds__(256) void pow_reduce_kernel() {
    int i = blockIdx.x * 256 + threadIdx.x;
    if (i >= BB*TT) return;
    int b = i >> 11;
    int t = i & 2047;
    float sum = 0.f;
    const float* base = d_pw + ((size_t)b * 32) * 2048 + t;
    for (int c = 0; c < 32; c++) sum += base[(size_t)c * 2048];
    d_Pm[i] = sum * (1.f / DD);
}

// ---------------- 4. inverse FFT -> autocorrelation ----------------
__global__ __launch_bounds__(1024) void ifft_kernel() {
    __shared__ float2 bufA[2048];
    __shared__ float2 bufB[2048];
    int b = blockIdx.x;
    const float* P = d_Pm + (size_t)b * 2048;
    for (int t = threadIdx.x; t < 2048; t += 1024)
        bufA[t] = make_float2(P[t], 0.f);
    __syncthreads();
    float2* src = bufA; float2* dst = bufB;
    for (int st = 0; st < 11; st++) {
        int m = 1 << st;
        int l = 1024 >> st;
        int i = threadIdx.x;
        int j = i >> st;
        float2 a = src[i];
        float2 bb = src[i + 1024];
        float2 s2 = make_float2(a.x + bb.x, a.y + bb.y);
        float2 d2 = make_float2(a.x - bb.x, a.y - bb.y);
        float2 w = d_tw[l + j];
        int o = i + (i & ~(m - 1));
        dst[o]     = s2;
        dst[o + m] = make_float2(w.x * d2.x - w.y * d2.y, w.x * d2.y + w.y * d2.x);
        __syncthreads();
        float2* tmp = src; src = dst; dst = tmp;
    }
    for (int t = threadIdx.x; t < 2048; t += 1024) {
        int ts = (t <= 1024) ? t : (2048 - t);
        d_r[(size_t)b * 2048 + t] = src[ts].x * (1.f / 2048.f);
    }
}

// ---------------- 5. top-k + softmax ----------------
__global__ __launch_bounds__(256) void topk_kernel() {
    int b = blockIdx.x;
    __shared__ float rv[2048];
    __shared__ float redv[256];
    __shared__ int   redi[256];
    __shared__ float vals[KTOP];
    int tid = threadIdx.x;
    for (int t = tid; t < 2048; t += 256) rv[t] = d_r[(size_t)b * 2048 + t];
    __syncthreads();
    if (tid == 0) rv[0] = -INFINITY;
    __syncthreads();
    for (int sel = 0; sel < KTOP; sel++) {
        float bv = -INFINITY; int bi = 0;
        for (int t = tid; t < 2048; t += 256) {
            float v = rv[t];
            if (v > bv) { bv = v; bi = t; }
        }
        redv[tid] = bv; redi[tid] = bi;
        __syncthreads();
        for (int off = 128; off > 0; off >>= 1) {
            if (tid < off) {
                float v2 = redv[tid + off]; int i2 = redi[tid + off];
                if (v2 > redv[tid] || (v2 == redv[tid] && i2 < redi[tid])) {
                    redv[tid] = v2; redi[tid] = i2;
                }
            }
            __syncthreads();
        }
        if (tid == 0) {
            vals[sel] = redv[0];
            int p = redi[0];
            int bk = b * KTOP + sel;
            d_p[bk] = p;
            int cyc = (TT + p - 1) / p;
            d_cyc[bk] = cyc;
            d_ucount[bk] = cyc * p;
            rv[p] = -INFINITY;
        }
        __syncthreads();
    }
    if (tid == 0) {
        float m = vals[0];
        for (int s = 1; s < KTOP; s++) m = fmaxf(m, vals[s]);
        float e[KTOP], sum = 0.f;
        for (int s = 0; s < KTOP; s++) { e[s] = expf(vals[s] - m); sum += e[s]; }
        for (int s = 0; s < KTOP; s++) d_wk[b * KTOP + s] = e[s] / sum;
    }
}

// ---------------- 6. gather ----------------
__global__ __launch_bounds__(256) void gather_kernel() {
    int bk = blockIdx.y;
    int ucount = d_ucount[bk];
    int p = d_p[bk];
    int b = bk / KTOP;
    int i = blockIdx.x * 256 + threadIdx.x;
    if (i >= UMAX * DD) return;
    int u = i >> 6;
    int c = i & 63;
    if (u >= ucount) return;
    int v = (u < TT) ? u : (2 * TT - 2 - u);
    int t = v + p;
    if (t >= TT) t -= TT;
    d_G[(size_t)bk * (UMAX * DD) + i] = d_s[((size_t)b * TT + t) * DD + c];
}

// ---------------- 7. mma.sync tf32 implicit-GEMM conv (occ-2) ----------------
__device__ __forceinline__ void ldsm4(uint32_t& r0, uint32_t& r1,
                                      uint32_t& r2, uint32_t& r3, uint32_t addr) {
    asm volatile("ldmatrix.sync.aligned.m8n8.x4.shared.b16 {%0,%1,%2,%3}, [%4];"
                 : "=r"(r0), "=r"(r1), "=r"(r2), "=r"(r3) : "r"(addr));
}

__global__ __launch_bounds__(256, 2) void conv_mma_kernel(
    const float* __restrict__ in, float* __restrict__ out,
    const uint2* __restrict__ WF,
    const float* __restrict__ gamma, const float* __restrict__ beta,
    const float* __restrict__ mean,  const float* __restrict__ var,
    int dogelu)
{
    __shared__ float    bn[128];
    __shared__ uint32_t As[128 * ASTR];

    int tid = threadIdx.x, wid = tid >> 5, lid = tid & 31;
    int gid = lid >> 2, tg = lid & 3;
    int wm = wid >> 1, wn = wid & 1;
    int bk = blockIdx.y;
    int ucount = d_ucount[bk];
    int u0 = blockIdx.x * 128;
    if (u0 >= ucount) return;
    int p = d_p[bk];
    int cyc = d_cyc[bk];

    if (tid < 64) {
        float sc = gamma[tid] * rsqrtf(var[tid] + EPSBN);
        bn[tid]      = sc;
        bn[64 + tid] = beta[tid] - mean[tid] * sc;
    }

    // ldmatrix source address (per lane), row-block for this warp
    uint32_t as_base;
    {
        uint64_t g = (uint64_t)__cvta_generic_to_shared(As);
        as_base = (uint32_t)g;
    }
    int lrow = wm * 32 + (lid & 15);
    int lcol = 4 * (lid >> 4);
    uint32_t addr0 = as_base + ((uint32_t)(lrow * ASTR + lcol) << 2);

    int urow = tid >> 1;
    int k0 = (tid & 1) * 32;
    int u = u0 + urow;
    bool inb = u < ucount;
    int r = inb ? (u / p) : 0;
    int c = u - r * p;

    float dacc[2][4][4];
#pragma unroll
    for (int mf = 0; mf < 2; mf++)
#pragma unroll
        for (int nf = 0; nf < 4; nf++)
#pragma unroll
            for (int j = 0; j < 4; j++) dacc[mf][nf][j] = 0.f;

#pragma unroll
    for (int tap = 0; tap < 9; tap++) {
        int dr = tap / 3 - 1;
        int dc = tap - (tap / 3) * 3 - 1;
        __syncthreads();
        // build A tile
        {
            bool valid = inb &&
                         (unsigned)(r + dr) < (unsigned)cyc &&
                         (unsigned)(c + dc) < (unsigned)p;
            int gu = valid ? (u + dr * p + dc) : 0;
            const float4* src =
                (const float4*)(in + ((size_t)bk * UMAX + gu) * 64 + k0);
            uint32_t* arow = As + urow * ASTR + k0;
#pragma unroll
            for (int f = 0; f < 8; f++) {
                float4 v = valid ? src[f] : make_float4(0.f, 0.f, 0.f, 0.f);
                uint4 o;
                o.x = f2tf32(v.x); o.y = f2tf32(v.y);
                o.z = f2tf32(v.z); o.w = f2tf32(v.w);
                *(uint4*)(arow + f * 4) = o;
            }
        }
        __syncthreads();
        const uint2* wf = WF + ((size_t)(tap * 8) * 8) * 32;
#pragma unroll
        for (int kk = 0; kk < 8; kk++) {
            uint32_t a[2][4];
#pragma unroll
            for (int mf = 0; mf < 2; mf++)
                ldsm4(a[mf][0], a[mf][1], a[mf][2], a[mf][3],
                      addr0 + (uint32_t)((mf * 16 * ASTR + kk * 8) << 2));
            const uint2* wfk = wf + (kk * 8 + wn * 4) * 32 + lid;
#pragma unroll
            for (int nf = 0; nf < 4; nf++) {
                uint2 bb = wfk[nf * 32];
#pragma unroll
                for (int mf = 0; mf < 2; mf++) {
                    asm volatile(
                        "mma.sync.aligned.m16n8k8.row.col.f32.tf32.tf32.f32 "
                        "{%0,%1,%2,%3}, {%4,%5,%6,%7}, {%8,%9}, {%0,%1,%2,%3};"
                        : "+f"(dacc[mf][nf][0]), "+f"(dacc[mf][nf][1]),
                          "+f"(dacc[mf][nf][2]), "+f"(dacc[mf][nf][3])
                        : "r"(a[mf][0]), "r"(a[mf][1]), "r"(a[mf][2]), "r"(a[mf][3]),
                          "r"(bb.x), "r"(bb.y));
                }
            }
        }
    }

    // epilogue: BN (+GELU) + store
#pragma unroll
    for (int mf = 0; mf < 2; mf++) {
        int row0 = u0 + wm * 32 + mf * 16 + gid;
#pragma unroll
        for (int nf = 0; nf < 4; nf++) {
            int col = wn * 32 + nf * 8 + 2 * tg;
            float sc0 = bn[col], sh0 = bn[64 + col];
            float sc1 = bn[col + 1], sh1 = bn[64 + col + 1];
#pragma unroll
            for (int h = 0; h < 2; h++) {
                int row = row0 + h * 8;
                if (row >= ucount) continue;
                float v0 = dacc[mf][nf][2 * h]     * sc0 + sh0;
                float v1 = dacc[mf][nf][2 * h + 1] * sc1 + sh1;
                if (dogelu) {
                    v0 = 0.5f * v0 * (1.f + erff(v0 * 0.7071067811865475f));
                    v1 = 0.5f * v1 * (1.f + erff(v1 * 0.7071067811865475f));
                }
                float2 o2; o2.x = v0; o2.y = v1;
                *(float2*)(out + ((size_t)bk * UMAX + row) * 64 + col) = o2;
            }
        }
    }
}

// ---------------- 8. weighted aggregation + residual ----------------
__global__ __launch_bounds__(256) void finalize_kernel(const float* __restrict__ x,
                                                       float* __restrict__ out) {
    int i = blockIdx.x * 256 + threadIdx.x;
    if (i >= BB*TT*DD) return;
    int b = i >> 17;
    int tc = i & (TT * DD - 1);
    float acc = x[i] + d_trend[i];
#pragma unroll
    for (int k = 0; k < KTOP; k++) {
        int bk = b * KTOP + k;
        size_t o = (size_t)bk * (UMAX * DD) + tc;
        acc += d_wk[bk] * (d_G[o] + d_H2[o]);
    }
    out[i] = acc;
}

// ---------------- launch ----------------
extern "C" void kernel_launch(void* const* d_in, const int* in_sizes, int n_in,
                              void* d_out, int out_size) {
    const float* x        = (const float*)d_in[0];
    const float* w1       = (const float*)d_in[1];
    const float* w2       = (const float*)d_in[2];
    const float* bn1_g    = (const float*)d_in[3];
    const float* bn1_b    = (const float*)d_in[4];
    const float* bn1_m    = (const float*)d_in[5];
    const float* bn1_v    = (const float*)d_in[6];
    const float* bn2_g    = (const float*)d_in[7];
    const float* bn2_b    = (const float*)d_in[8];
    const float* bn2_m    = (const float*)d_in[9];
    const float* bn2_v    = (const float*)d_in[10];
    float* out = (float*)d_out;

    float* G;  cudaGetSymbolAddress((void**)&G,  d_G);
    float* H1; cudaGetSymbolAddress((void**)&H1, d_H1);
    float* H2; cudaGetSymbolAddress((void**)&H2, d_H2);
    uint2* WF; cudaGetSymbolAddress((void**)&WF, d_WF);

    twiddle_kernel<<<8, 256>>>();
    wfrag_kernel<<<(2*9*8*8*32 + 255) / 256, 256>>>(w1, w2);
    trend_kernel<<<(BB*TT*DD + 255) / 256, 256>>>(x);
    fft_power_kernel<<<BB * 32, 256>>>();
    pow_reduce_kernel<<<(BB*TT + 255) / 256, 256>>>();
    ifft_kernel<<<BB, 1024>>>();
    topk_kernel<<<BB, 256>>>();
    gather_kernel<<<dim3((UMAX * DD + 255) / 256, BK), 256>>>();
    conv_mma_kernel<<<dim3(32, BK), 256>>>(G, H1, WF,             bn1_g, bn1_b, bn1_m, bn1_v, 1);
    conv_mma_kernel<<<dim3(32, BK), 256>>>(H1, H2, WF + 9*8*8*32, bn2_g, bn2_b, bn2_m, bn2_v, 0);
    finalize_kernel<<<(BB*TT*DD + 255) / 256, 256>>>(x, out);
}

// round 17
// speedup vs baseline: 10.8687x; 2.1227x over previous
#include <cuda_runtime.h>
#include <cuda_fp16.h>
#include <math.h>
#include <stdint.h>

#define BB 8
#define TT 2048
#define DD 64
#define KTOP 5
#define BK (BB*KTOP)
#define UMAX 4094
#define EPSBN 1e-5f

#define SEGSTR 72            // halfs per row (64 + 8 pad)
#define SEGROWS 130
#define SEGSZ (SEGROWS*SEGSTR)
#define CONV_SMEM (3*SEGSZ*2)    /* 56160 bytes */
#define WFN (9*4*8*32)           /* uint2 entries per conv */

// ---------------- scratch (device globals; no allocs allowed) ----------------
__device__ float d_trend[BB*TT*DD];
__device__ float d_s[BB*TT*DD];
__device__ float d_pw[BB*DD*TT];
__device__ float d_Pm[BB*TT];
__device__ float d_r[BB*TT];
__device__ int   d_p[BK];
__device__ int   d_cyc[BK];
__device__ int   d_ucount[BK];
__device__ float d_wk[BK];
__device__ float d_H1[BK*UMAX*DD];
__device__ float d_H2[BK*UMAX*DD];
__device__ float2 d_tw[2048];
__device__ uint2  d_WF[2*WFN];   // fp16 B-frags: [conv][tap][kk][nf][lane]

// ---------------- 0a. twiddle table ----------------
__global__ __launch_bounds__(256) void twiddle_kernel() {
    int i = blockIdx.x * 256 + threadIdx.x;
    if (i >= 2048) return;
    if (i == 0) { d_tw[0] = make_float2(1.f, 0.f); return; }
    int l = 1 << (31 - __clz(i));
    int j = i - l;
    float ang = (-3.14159265358979323846f) * (float)j / (float)l;
    float sw, cw; sincosf(ang, &sw, &cw);
    d_tw[i] = make_float2(cw, sw);
}

// ---------------- 0b. fp16 weight fragment table ----------------
__global__ __launch_bounds__(256) void wfrag_kernel(const float* __restrict__ w1,
                                                    const float* __restrict__ w2) {
    int i = blockIdx.x * 256 + threadIdx.x;
    if (i >= 2*WFN) return;
    int lane = i & 31;
    int nf   = (i >> 5) & 7;
    int kk   = (i >> 8) & 3;
    int tap  = (i >> 10) % 9;
    int cw   = i / WFN;
    const float* W = cw ? w2 : w1;
    int n  = nf * 8 + (lane >> 2);
    int t  = lane & 3;
    int k0 = kk * 16 + 2 * t;
    __half2 h0 = __floats2half2_rn(W[((size_t)(n*64 + k0    ))*9 + tap],
                                   W[((size_t)(n*64 + k0 + 1))*9 + tap]);
    __half2 h1 = __floats2half2_rn(W[((size_t)(n*64 + k0 + 8))*9 + tap],
                                   W[((size_t)(n*64 + k0 + 9))*9 + tap]);
    uint2 v;
    v.x = *(uint32_t*)&h0;
    v.y = *(uint32_t*)&h1;
    d_WF[i] = v;
}

// ---------------- 1. trend + seasonal ----------------
__global__ __launch_bounds__(256) void trend_kernel(const float* __restrict__ x) {
    int i = blockIdx.x * 256 + threadIdx.x;
    if (i >= BB*TT*DD) return;
    int c = i & 63;
    int t = (i >> 6) & (TT - 1);
    int b = i >> 17;
    int lo = t - 12; if (lo < 0) lo = 0;
    int hi = t + 12; if (hi > TT - 1) hi = TT - 1;
    const float* xb = x + ((size_t)b * TT) * DD + c;
    float sum = 0.f;
    for (int tt = lo; tt <= hi; tt++) sum += xb[(size_t)tt * DD];
    float tr = sum / (float)(hi - lo + 1);
    d_trend[i] = tr;
    d_s[i] = x[i] - tr;
}

// ---------------- 2. forward FFT (2 channels packed) + power ----------------
__global__ __launch_bounds__(256) void fft_power_kernel() {
    __shared__ float2 bufA[2048];
    __shared__ float2 bufB[2048];
    int b = blockIdx.x >> 5;
    int pr = blockIdx.x & 31;
    const float2* sp = (const float2*)d_s + ((size_t)b * TT) * 32 + pr;
    for (int t = threadIdx.x; t < 2048; t += 256)
        bufA[t] = sp[(size_t)t * 32];
    __syncthreads();
    float2* src = bufA; float2* dst = bufB;
    for (int st = 0; st < 11; st++) {
        int m = 1 << st;
        int l = 1024 >> st;
        for (int i = threadIdx.x; i < 1024; i += 256) {
            int j = i >> st;
            float2 a = src[i];
            float2 bb = src[i + 1024];
            float2 s2 = make_float2(a.x + bb.x, a.y + bb.y);
            float2 d2 = make_float2(a.x - bb.x, a.y - bb.y);
            float2 w = d_tw[l + j];
            int o = i + (i & ~(m - 1));
            dst[o]     = s2;
            dst[o + m] = make_float2(w.x * d2.x - w.y * d2.y, w.x * d2.y + w.y * d2.x);
        }
        __syncthreads();
        float2* tmp = src; src = dst; dst = tmp;
    }
    float* out = d_pw + (size_t)blockIdx.x * 2048;
    for (int t = threadIdx.x; t < 2048; t += 256) {
        float2 X0 = src[t];
        float2 X1 = src[(2048 - t) & 2047];
        out[t] = 0.5f * (X0.x * X0.x + X0.y * X0.y + X1.x * X1.x + X1.y * X1.y);
    }
}

// ---------------- 3. mean over channel pairs ----------------
__global__ __launch_bounds__(256) void pow_reduce_kernel() {
    int i = blockIdx.x * 256 + threadIdx.x;
    if (i >= BB*TT) return;
    int b = i >> 11;
    int t = i & 2047;
    float sum = 0.f;
    const float* base = d_pw + ((size_t)b * 32) * 2048 + t;
    for (int c = 0; c < 32; c++) sum += base[(size_t)c * 2048];
    d_Pm[i] = sum * (1.f / DD);
}

// ---------------- 4. inverse FFT -> autocorrelation ----------------
__global__ __launch_bounds__(1024) void ifft_kernel() {
    __shared__ float2 bufA[2048];
    __shared__ float2 bufB[2048];
    int b = blockIdx.x;
    const float* P = d_Pm + (size_t)b * 2048;
    for (int t = threadIdx.x; t < 2048; t += 1024)
        bufA[t] = make_float2(P[t], 0.f);
    __syncthreads();
    float2* src = bufA; float2* dst = bufB;
    for (int st = 0; st < 11; st++) {
        int m = 1 << st;
        int l = 1024 >> st;
        int i = threadIdx.x;
        int j = i >> st;
        float2 a = src[i];
        float2 bb = src[i + 1024];
        float2 s2 = make_float2(a.x + bb.x, a.y + bb.y);
        float2 d2 = make_float2(a.x - bb.x, a.y - bb.y);
        float2 w = d_tw[l + j];
        int o = i + (i & ~(m - 1));
        dst[o]     = s2;
        dst[o + m] = make_float2(w.x * d2.x - w.y * d2.y, w.x * d2.y + w.y * d2.x);
        __syncthreads();
        float2* tmp = src; src = dst; dst = tmp;
    }
    for (int t = threadIdx.x; t < 2048; t += 1024) {
        int ts = (t <= 1024) ? t : (2048 - t);
        d_r[(size_t)b * 2048 + t] = src[ts].x * (1.f / 2048.f);
    }
}

// ---------------- 5. top-k + softmax ----------------
__global__ __launch_bounds__(256) void topk_kernel() {
    int b = blockIdx.x;
    __shared__ float rv[2048];
    __shared__ float redv[256];
    __shared__ int   redi[256];
    __shared__ float vals[KTOP];
    int tid = threadIdx.x;
    for (int t = tid; t < 2048; t += 256) rv[t] = d_r[(size_t)b * 2048 + t];
    __syncthreads();
    if (tid == 0) rv[0] = -INFINITY;
    __syncthreads();
    for (int sel = 0; sel < KTOP; sel++) {
        float bv = -INFINITY; int bi = 0;
        for (int t = tid; t < 2048; t += 256) {
            float v = rv[t];
            if (v > bv) { bv = v; bi = t; }
        }
        redv[tid] = bv; redi[tid] = bi;
        __syncthreads();
        for (int off = 128; off > 0; off >>= 1) {
            if (tid < off) {
                float v2 = redv[tid + off]; int i2 = redi[tid + off];
                if (v2 > redv[tid] || (v2 == redv[tid] && i2 < redi[tid])) {
                    redv[tid] = v2; redi[tid] = i2;
                }
            }
            __syncthreads();
        }
        if (tid == 0) {
            vals[sel] = redv[0];
            int p = redi[0];
            int bk = b * KTOP + sel;
            d_p[bk] = p;
            int cyc = (TT + p - 1) / p;
            d_cyc[bk] = cyc;
            d_ucount[bk] = cyc * p;
            rv[p] = -INFINITY;
        }
        __syncthreads();
    }
    if (tid == 0) {
        float m = vals[0];
        for (int s = 1; s < KTOP; s++) m = fmaxf(m, vals[s]);
        float e[KTOP], sum = 0.f;
        for (int s = 0; s < KTOP; s++) { e[s] = expf(vals[s] - m); sum += e[s]; }
        for (int s = 0; s < KTOP; s++) d_wk[b * KTOP + s] = e[s] / sum;
    }
}

// ---------------- 7. fp16 mma implicit-GEMM conv, 3-segment staging ----------
__device__ __forceinline__ void ldsm4(uint32_t& r0, uint32_t& r1,
                                      uint32_t& r2, uint32_t& r3, uint32_t addr) {
    asm volatile("ldmatrix.sync.aligned.m8n8.x4.shared.b16 {%0,%1,%2,%3}, [%4];"
                 : "=r"(r0), "=r"(r1), "=r"(r2), "=r"(r3) : "r"(addr));
}

__global__ __launch_bounds__(256, 2) void conv_mma_kernel(
    const float* __restrict__ in, float* __restrict__ out,
    const uint2* __restrict__ WF,
    const float* __restrict__ gamma, const float* __restrict__ beta,
    const float* __restrict__ mean,  const float* __restrict__ var,
    int gmode, int dogelu)
{
    extern __shared__ __align__(16) char smem_raw[];
    __half* As = (__half*)smem_raw;
    __shared__ float bn[128];

    int tid = threadIdx.x, wid = tid >> 5, lid = tid & 31;
    int gid = lid >> 2, tg = lid & 3;
    int wm = wid >> 1, wn = wid & 1;
    int bk = blockIdx.y;
    int b  = bk / KTOP;
    int ucount = d_ucount[bk];
    int u0 = blockIdx.x * 128;
    if (u0 >= ucount) return;
    int p = d_p[bk];
    int cyc = d_cyc[bk];

    if (tid < 64) {
        float sc = gamma[tid] * rsqrtf(var[tid] + EPSBN);
        bn[tid]      = sc;
        bn[64 + tid] = beta[tid] - mean[tid] * sc;
    }

    // ---- build 3 row segments (dr = -1, 0, +1), fp16, roll/reflect fused ----
#pragma unroll
    for (int seg = 0; seg < 3; seg++) {
        int base_gu = u0 + (seg - 1) * p - 1;
        __half* segp = As + seg * SEGSZ;
        for (int idx = tid; idx < SEGROWS * 8; idx += 256) {
            int row = idx >> 3, oct = idx & 7;
            int gu = base_gu + row;
            gu = min(max(gu, 0), ucount - 1);
            size_t roff;
            if (gmode) {
                int v = (gu < TT) ? gu : (2 * TT - 2 - gu);
                int srow = v + p; if (srow >= TT) srow -= TT;
                roff = (size_t)b * TT + srow;
            } else {
                roff = (size_t)bk * UMAX + gu;
            }
            const float4* sp = (const float4*)(in + roff * 64 + oct * 8);
            float4 va = sp[0], vb = sp[1];
            __half2 h0 = __floats2half2_rn(va.x, va.y);
            __half2 h1 = __floats2half2_rn(va.z, va.w);
            __half2 h2 = __floats2half2_rn(vb.x, vb.y);
            __half2 h3 = __floats2half2_rn(vb.z, vb.w);
            uint4 o;
            o.x = *(uint32_t*)&h0; o.y = *(uint32_t*)&h1;
            o.z = *(uint32_t*)&h2; o.w = *(uint32_t*)&h3;
            *(uint4*)(segp + row * SEGSTR + oct * 8) = o;
        }
    }
    __syncthreads();

    // my 4 output rows: [mf][h]
    int rr[2][2], cc[2][2];
#pragma unroll
    for (int mf = 0; mf < 2; mf++)
#pragma unroll
        for (int h = 0; h < 2; h++) {
            int u = u0 + wm * 32 + mf * 16 + gid + h * 8;
            int r = u / p;
            rr[mf][h] = r;
            cc[mf][h] = u - r * p;
        }

    uint32_t asb = (uint32_t)__cvta_generic_to_shared(As);
    uint32_t lanepart = (uint32_t)(((lid & 15) * SEGSTR) * 2 + (lid >> 4) * 16);

    float dacc[2][4][4];
#pragma unroll
    for (int mf = 0; mf < 2; mf++)
#pragma unroll
        for (int nf = 0; nf < 4; nf++)
#pragma unroll
            for (int j = 0; j < 4; j++) dacc[mf][nf][j] = 0.f;

#pragma unroll
    for (int tap = 0; tap < 9; tap++) {
        int dr = tap / 3 - 1;
        int dc = tap - (tap / 3) * 3 - 1;
        int seg = dr + 1;
        bool vv[2][2];
#pragma unroll
        for (int mf = 0; mf < 2; mf++)
#pragma unroll
            for (int h = 0; h < 2; h++)
                vv[mf][h] = (unsigned)(rr[mf][h] + dr) < (unsigned)cyc &&
                            (unsigned)(cc[mf][h] + dc) < (unsigned)p;
        uint32_t base0 = asb +
            (uint32_t)((seg * SEGSZ + (wm * 32 + 1 + dc) * SEGSTR) * 2) + lanepart;
#pragma unroll
        for (int kk = 0; kk < 4; kk++) {
            uint32_t a[2][4];
#pragma unroll
            for (int mf = 0; mf < 2; mf++) {
                ldsm4(a[mf][0], a[mf][1], a[mf][2], a[mf][3],
                      base0 + (uint32_t)((mf * 16 * SEGSTR) * 2 + kk * 32));
                if (!vv[mf][0]) { a[mf][0] = 0u; a[mf][2] = 0u; }
                if (!vv[mf][1]) { a[mf][1] = 0u; a[mf][3] = 0u; }
            }
            const uint2* wfk = WF + ((tap * 4 + kk) * 8 + wn * 4) * 32 + lid;
#pragma unroll
            for (int nf = 0; nf < 4; nf++) {
                uint2 bb = wfk[nf * 32];
#pragma unroll
                for (int mf = 0; mf < 2; mf++) {
                    asm volatile(
                        "mma.sync.aligned.m16n8k16.row.col.f32.f16.f16.f32 "
                        "{%0,%1,%2,%3}, {%4,%5,%6,%7}, {%8,%9}, {%0,%1,%2,%3};"
                        : "+f"(dacc[mf][nf][0]), "+f"(dacc[mf][nf][1]),
                          "+f"(dacc[mf][nf][2]), "+f"(dacc[mf][nf][3])
                        : "r"(a[mf][0]), "r"(a[mf][1]), "r"(a[mf][2]), "r"(a[mf][3]),
                          "r"(bb.x), "r"(bb.y));
                }
            }
        }
    }

    // epilogue: BN (+GELU) + store
#pragma unroll
    for (int mf = 0; mf < 2; mf++) {
        int row0 = u0 + wm * 32 + mf * 16 + gid;
#pragma unroll
        for (int nf = 0; nf < 4; nf++) {
            int col = wn * 32 + nf * 8 + 2 * tg;
            float sc0 = bn[col], sh0 = bn[64 + col];
            float sc1 = bn[col + 1], sh1 = bn[64 + col + 1];
#pragma unroll
            for (int h = 0; h < 2; h++) {
                int row = row0 + h * 8;
                if (row >= ucount) continue;
                float v0 = dacc[mf][nf][2 * h]     * sc0 + sh0;
                float v1 = dacc[mf][nf][2 * h + 1] * sc1 + sh1;
                if (dogelu) {
                    v0 = 0.5f * v0 * (1.f + erff(v0 * 0.7071067811865475f));
                    v1 = 0.5f * v1 * (1.f + erff(v1 * 0.7071067811865475f));
                }
                float2 o2; o2.x = v0; o2.y = v1;
                *(float2*)(out + ((size_t)bk * UMAX + row) * 64 + col) = o2;
            }
        }
    }
}

// ---------------- 8. weighted aggregation + residual (gather fused) ----------
__global__ __launch_bounds__(256) void finalize_kernel(const float* __restrict__ x,
                                                       float* __restrict__ out) {
    int i = blockIdx.x * 256 + threadIdx.x;
    if (i >= BB*TT*DD) return;
    int b = i >> 17;
    int tc = i & (TT * DD - 1);
    int t = tc >> 6;
    int c = tc & 63;
    float acc = x[i] + d_trend[i];
#pragma unroll
    for (int k = 0; k < KTOP; k++) {
        int bk = b * KTOP + k;
        int p = d_p[bk];
        int srow = t + p; if (srow >= TT) srow -= TT;
        float g = d_s[((size_t)b * TT + srow) * 64 + c];
        acc += d_wk[bk] * (g + d_H2[(size_t)bk * (UMAX * DD) + tc]);
    }
    out[i] = acc;
}

// ---------------- launch ----------------
extern "C" void kernel_launch(void* const* d_in, const int* in_sizes, int n_in,
                              void* d_out, int out_size) {
    const float* x        = (const float*)d_in[0];
    const float* w1       = (const float*)d_in[1];
    const float* w2       = (const float*)d_in[2];
    const float* bn1_g    = (const float*)d_in[3];
    const float* bn1_b    = (const float*)d_in[4];
    const float* bn1_m    = (const float*)d_in[5];
    const float* bn1_v    = (const float*)d_in[6];
    const float* bn2_g    = (const float*)d_in[7];
    const float* bn2_b    = (const float*)d_in[8];
    const float* bn2_m    = (const float*)d_in[9];
    const float* bn2_v    = (const float*)d_in[10];
    float* out = (float*)d_out;

    float* S;  cudaGetSymbolAddress((void**)&S,  d_s);
    float* H1; cudaGetSymbolAddress((void**)&H1, d_H1);
    float* H2; cudaGetSymbolAddress((void**)&H2, d_H2);
    uint2* WF; cudaGetSymbolAddress((void**)&WF, d_WF);

    cudaFuncSetAttribute(conv_mma_kernel,
                         cudaFuncAttributeMaxDynamicSharedMemorySize, CONV_SMEM);

    twiddle_kernel<<<8, 256>>>();
    wfrag_kernel<<<(2*WFN + 255) / 256, 256>>>(w1, w2);
    trend_kernel<<<(BB*TT*DD + 255) / 256, 256>>>(x);
    fft_power_kernel<<<BB * 32, 256>>>();
    pow_reduce_kernel<<<(BB*TT + 255) / 256, 256>>>();
    ifft_kernel<<<BB, 1024>>>();
    topk_kernel<<<BB, 256>>>();
    conv_mma_kernel<<<dim3(32, BK), 256, CONV_SMEM>>>(S,  H1, WF,       bn1_g, bn1_b, bn1_m, bn1_v, 1, 1);
    conv_mma_kernel<<<dim3(32, BK), 256, CONV_SMEM>>>(H1, H2, WF + WFN, bn2_g, bn2_b, bn2_m, bn2_v, 0, 0);
    finalize_kernel<<<(BB*TT*DD + 255) / 256, 256>>>(x, out);
}